// round 12
// baseline (speedup 1.0000x reference)
#include <cuda_runtime.h>
#include <cuda_fp16.h>
#include <cstdint>

#define SEQ    4096
#define DMODEL 512
#define NH     8
#define HD     64
#define KDIM   512
#define NW     (SEQ / 32)   // 128 mask words per row

#define BM 64
#define BN 64
#define NKB (SEQ / BN)

// 0.125 * log2(e): folded into Q projection so flash does exp2(S) directly
#define QSCALE 0.18033688011112042f

// ---------------- scratch (device globals; no allocation allowed) ----------------
__device__ __half   g_Xh[SEQ * KDIM];          // fp16 copy of x
__device__ __half   g_Wh[4 * DMODEL * KDIM];   // wq, wk, wv, dense (fp16)
__device__ __half   g_Qh[SEQ * DMODEL];        // pre-scaled by QSCALE
__device__ __half   g_Kh[SEQ * DMODEL];
__device__ __half   g_Vh[SEQ * DMODEL];
__device__ __half   g_Ch[SEQ * DMODEL];        // context (head-major), fp16
__device__ unsigned g_mb[SEQ * NW];

// ================= helpers =================
__device__ __forceinline__ uint32_t smem_u32(const void* p) {
    uint32_t a;
    asm("{ .reg .u64 t; cvta.to.shared.u64 t, %1; cvt.u32.u64 %0, t; }" : "=r"(a) : "l"(p));
    return a;
}
__device__ __forceinline__ void cp16(uint32_t dst, const void* src) {
    asm volatile("cp.async.cg.shared.global [%0], [%1], 16;" :: "r"(dst), "l"(src));
}
__device__ __forceinline__ void cp_commit() { asm volatile("cp.async.commit_group;"); }
__device__ __forceinline__ void cp_wait0()  { asm volatile("cp.async.wait_group 0;" ::: "memory"); }
__device__ __forceinline__ void cp_wait1()  { asm volatile("cp.async.wait_group 1;" ::: "memory"); }

__device__ __forceinline__ void ldsm4(uint32_t* r, uint32_t addr) {
    asm volatile("ldmatrix.sync.aligned.m8n8.x4.shared.b16 {%0,%1,%2,%3}, [%4];"
        : "=r"(r[0]), "=r"(r[1]), "=r"(r[2]), "=r"(r[3]) : "r"(addr));
}
__device__ __forceinline__ void ldsm4t(uint32_t* r, uint32_t addr) {
    asm volatile("ldmatrix.sync.aligned.m8n8.x4.trans.shared.b16 {%0,%1,%2,%3}, [%4];"
        : "=r"(r[0]), "=r"(r[1]), "=r"(r[2]), "=r"(r[3]) : "r"(addr));
}
// D = A*B + D   (m16n8k16, f16 in, f32 accum)
__device__ __forceinline__ void mma16816(float* d, const uint32_t* a, const uint32_t* b) {
    asm volatile("mma.sync.aligned.m16n8k16.row.col.f32.f16.f16.f32 "
        "{%0,%1,%2,%3}, {%4,%5,%6,%7}, {%8,%9}, {%0,%1,%2,%3};"
        : "+f"(d[0]), "+f"(d[1]), "+f"(d[2]), "+f"(d[3])
        : "r"(a[0]), "r"(a[1]), "r"(a[2]), "r"(a[3]), "r"(b[0]), "r"(b[1]));
}
__device__ __forceinline__ uint32_t pack_h2(float a, float b) {
    __half2 h = __floats2half2_rn(a, b);
    return *reinterpret_cast<uint32_t*>(&h);
}
// 2^x on the MUFU pipe
__device__ __forceinline__ float ex2(float x) {
    float y;
    asm("ex2.approx.ftz.f32 %0, %1;" : "=f"(y) : "f"(x));
    return y;
}

// ---------------- convert: x + 4 weight matrices -> fp16 ----------------
__global__ __launch_bounds__(256) void convert_kernel(
    const float* __restrict__ x,  const float* __restrict__ wq,
    const float* __restrict__ wk, const float* __restrict__ wv,
    const float* __restrict__ dw)
{
    int f4 = blockIdx.x * 256 + threadIdx.x;   // 0 .. 786431
    const float4* src; __half* dst; int off;
    if (f4 < 524288) { src = (const float4*)x; off = f4; dst = g_Xh; }
    else {
        int t = f4 - 524288;
        int w = t >> 16; off = t & 65535;
        src = (const float4*)(w == 0 ? wq : w == 1 ? wk : w == 2 ? wv : dw);
        dst = g_Wh + w * (DMODEL * KDIM);
    }
    float4 v = src[off];
    uint2 u = { pack_h2(v.x, v.y), pack_h2(v.z, v.w) };
    *reinterpret_cast<uint2*>(dst + off * 4) = u;
}

// ---------------- mask pack: int32 [S,S] -> bitmask ----------------
__global__ void mask_pack_kernel(const int* __restrict__ mask)
{
    int gid = blockIdx.x * 256 + threadIdx.x;
    int v = mask[gid];
    unsigned b = __ballot_sync(0xffffffffu, v != 0);
    if ((threadIdx.x & 31) == 0) g_mb[gid >> 5] = b;
}

// ---------------- HMMA GEMM: out = (A @ W^T + bias) * scale ----------------
#define GP 40

template<bool DENSE>
__global__ __launch_bounds__(256) void hmma_gemm_kernel(
    float* __restrict__ outf, const float* __restrict__ dense_b,
    const float* __restrict__ bq, const float* __restrict__ bk,
    const float* __restrict__ bv)
{
    __shared__ __half sA[2][128 * GP];
    __shared__ __half sB[2][128 * GP];

    const int tid = threadIdx.x, lane = tid & 31, wid = tid >> 5;
    const int wm = wid & 1, wn = wid >> 1;
    const int m0 = blockIdx.y * 128, n0 = blockIdx.x * 128;
    const int z = DENSE ? 3 : blockIdx.z;

    const __half* W = g_Wh + z * (DMODEL * KDIM);
    const float* bias = DENSE ? dense_b : (z == 0 ? bq : z == 1 ? bk : bv);
    __half* outh = DENSE ? nullptr : (z == 0 ? g_Qh : z == 1 ? g_Kh : g_Vh);
    const float scale = (!DENSE && z == 0) ? QSCALE : 1.0f;

    const uint32_t sbA = smem_u32(sA), sbB = smem_u32(sB);

    float acc[4][4][4];
    #pragma unroll
    for (int mi = 0; mi < 4; mi++)
        #pragma unroll
        for (int g = 0; g < 4; g++)
            #pragma unroll
            for (int e = 0; e < 4; e++) acc[mi][g][e] = 0.0f;

    const uint32_t abase = ((((lane >> 3) & 1) * 8 + (lane & 7)) * GP) * 2 + ((lane >> 4) & 1) * 16;
    const uint32_t kbase = ((((lane >> 4) & 1) * 8 + (lane & 7)) * GP) * 2 + ((lane >> 3) & 1) * 16;

    #define LOAD_STAGE(kt, buf) do {                                                        \
        const int k0_ = (kt) * 32;                                                          \
        _Pragma("unroll")                                                                   \
        for (int l = 0; l < 2; l++) {                                                       \
            int idx = tid + l * 256;                                                        \
            int r = idx >> 2, c = idx & 3;                                                  \
            const __half* asrc = DENSE                                                      \
                ? (g_Ch + (k0_ >> 6) * (SEQ * HD) + (m0 + r) * HD + (k0_ & 63) + c * 8)     \
                : (g_Xh + (m0 + r) * KDIM + k0_ + c * 8);                                   \
            cp16(sbA + ((buf) * 128 * GP + r * GP) * 2 + c * 16, asrc);                     \
            cp16(sbB + ((buf) * 128 * GP + r * GP) * 2 + c * 16,                            \
                 W + (n0 + r) * KDIM + k0_ + c * 8);                                        \
        }                                                                                   \
        cp_commit();                                                                        \
    } while (0)

    LOAD_STAGE(0, 0);

    for (int kt = 0; kt < KDIM / 32; kt++) {
        const int buf = kt & 1;
        if (kt + 1 < KDIM / 32) { LOAD_STAGE(kt + 1, buf ^ 1); cp_wait1(); }
        else cp_wait0();
        __syncthreads();

        const uint32_t aw = sbA + (buf * 128 * GP + wm * 64 * GP) * 2;
        const uint32_t bw = sbB + (buf * 128 * GP + wn * 32 * GP) * 2;
        #pragma unroll
        for (int t = 0; t < 2; t++) {
            uint32_t Af[4][4];
            #pragma unroll
            for (int mi = 0; mi < 4; mi++)
                ldsm4(Af[mi], aw + (mi * 16 * GP) * 2 + t * 32 + abase);
            uint32_t Bf[2][4];
            #pragma unroll
            for (int bi = 0; bi < 2; bi++)
                ldsm4(Bf[bi], bw + (bi * 16 * GP) * 2 + t * 32 + kbase);
            #pragma unroll
            for (int mi = 0; mi < 4; mi++)
                #pragma unroll
                for (int bi = 0; bi < 2; bi++) {
                    mma16816(acc[mi][bi * 2],     Af[mi], Bf[bi]);
                    mma16816(acc[mi][bi * 2 + 1], Af[mi], Bf[bi] + 2);
                }
        }
        __syncthreads();
    }
    #undef LOAD_STAGE

    const int qr = lane >> 2, qc = (lane & 3) << 1;
    #pragma unroll
    for (int mi = 0; mi < 4; mi++) {
        int mrow = m0 + wm * 64 + mi * 16 + qr;
        #pragma unroll
        for (int g = 0; g < 4; g++) {
            int n = n0 + wn * 32 + g * 8 + qc;
            float b0 = bias[n], b1 = bias[n + 1];
            if (DENSE) {
                float2 u0 = { acc[mi][g][0] + b0, acc[mi][g][1] + b1 };
                float2 u1 = { acc[mi][g][2] + b0, acc[mi][g][3] + b1 };
                *reinterpret_cast<float2*>(outf + mrow * DMODEL + n)       = u0;
                *reinterpret_cast<float2*>(outf + (mrow + 8) * DMODEL + n) = u1;
            } else {
                uint32_t u0 = pack_h2((acc[mi][g][0] + b0) * scale, (acc[mi][g][1] + b1) * scale);
                uint32_t u1 = pack_h2((acc[mi][g][2] + b0) * scale, (acc[mi][g][3] + b1) * scale);
                *reinterpret_cast<uint32_t*>(outh + mrow * DMODEL + n)       = u0;
                *reinterpret_cast<uint32_t*>(outh + (mrow + 8) * DMODEL + n) = u1;
            }
        }
    }
}

// ---------------- fp16 mma.sync flash attention (pipelined, 2 warps x 32 q-rows) ----------------
// BM=64, 64 threads (2 warps, 32 q-rows each), 4 CTAs/SM -> 512-CTA grid in ONE wave.
// Cheap 2-warp barriers; 4 independent CTAs per SM decorrelate softmax vs MMA phases.
#define QPITCH 144
#define OFF_Q   0
#define OFF_K0  (64 * QPITCH)
#define OFF_K1  (OFF_K0 + 64 * QPITCH)
#define OFF_V0  (OFF_K1 + 64 * QPITCH)
#define OFF_V1  (OFF_V0 + 64 * QPITCH)
#define FL_SMEM (OFF_V1 + 64 * QPITCH)         // 5*64*144 = 46080 B

__global__ void __launch_bounds__(64, 4) flash_mma_kernel()
{
    extern __shared__ __align__(128) char smem[];
    const uint32_t sb = smem_u32(smem);
    const int tid  = threadIdx.x;
    const int wid  = tid >> 5;
    const int lane = tid & 31;
    const int h    = blockIdx.y;
    const int q0   = blockIdx.x * BM;
    const __half* Qg = g_Qh + h * (SEQ * HD);
    const __half* Kg = g_Kh + h * (SEQ * HD);
    const __half* Vg = g_Vh + h * (SEQ * HD);

    // ---- prologue: Q -> smem (padded); K0,V0 (group), K1 (group) ----
    {
        int r = tid;                              // 64 rows, one per thread
        const uint4* src = reinterpret_cast<const uint4*>(Qg + (q0 + r) * HD);
        char* dst = smem + OFF_Q + r * QPITCH;
        #pragma unroll
        for (int k = 0; k < 8; k++)
            reinterpret_cast<uint4*>(dst)[k] = src[k];
    }
    #pragma unroll
    for (int l = 0; l < 8; l++) {
        int idx = tid + l * 64;                   // 0..511
        int r = idx >> 3, ch = (idx & 7) << 3;
        cp16(sb + OFF_K0 + r * QPITCH + ch * 2, Kg + r * HD + ch);
        cp16(sb + OFF_V0 + r * QPITCH + ch * 2, Vg + r * HD + ch);
    }
    cp_commit();
    #pragma unroll
    for (int l = 0; l < 8; l++) {
        int idx = tid + l * 64;
        int r = idx >> 3, ch = (idx & 7) << 3;
        cp16(sb + OFF_K1 + r * QPITCH + ch * 2, Kg + BN * HD + r * HD + ch);
    }
    cp_commit();
    cp_wait0();
    __syncthreads();

    const int qb = wid * 32;
    const uint32_t abase = ((((lane >> 3) & 1) * 8 + (lane & 7)) * QPITCH) + (((lane >> 4) & 1) * 16);
    const uint32_t kbase = ((((lane >> 4) & 1) * 8 + (lane & 7)) * QPITCH) + (((lane >> 3) & 1) * 16);

    uint32_t Aq[2][4][4];
    #pragma unroll
    for (int u = 0; u < 2; u++)
        #pragma unroll
        for (int t = 0; t < 4; t++)
            ldsm4(Aq[u][t], sb + OFF_Q + (qb + u * 16) * QPITCH + t * 32 + abase);

    float Oacc[2][8][4];
    #pragma unroll
    for (int u = 0; u < 2; u++)
        #pragma unroll
        for (int j = 0; j < 8; j++)
            #pragma unroll
            for (int e = 0; e < 4; e++) Oacc[u][j][e] = 0.0f;

    // ---- issue QK(0) from Kbuf0 (B-frag shared across both row-tiles) ----
    float S[2][8][4];
    #pragma unroll
    for (int u = 0; u < 2; u++)
        #pragma unroll
        for (int j = 0; j < 8; j++)
            #pragma unroll
            for (int e = 0; e < 4; e++) S[u][j][e] = 0.0f;
    #pragma unroll
    for (int jp = 0; jp < 4; jp++) {
        #pragma unroll
        for (int t = 0; t < 4; t++) {
            uint32_t B[4];
            ldsm4(B, sb + OFF_K0 + jp * (16 * QPITCH) + t * 32 + kbase);
            #pragma unroll
            for (int u = 0; u < 2; u++) {
                mma16816(S[u][2 * jp],     Aq[u][t], B);
                mma16816(S[u][2 * jp + 1], Aq[u][t], B + 2);
            }
        }
    }
    __syncthreads();   // LDSM(K0) done in both warps before iter-0 prefetch overwrites Kbuf0

    const int rowb = q0 + qb + (lane >> 2);
    const int qv = lane & 3;
    float lsum[2][2] = { {0.0f, 0.0f}, {0.0f, 0.0f} };

    for (int i = 0; i < NKB; i++) {
        // --- prefetch K(i+2) -> kbuf[i&1], V(i+1) -> vbuf[(i+1)&1] ---
        if (i + 2 < NKB) {
            const uint32_t kn = sb + ((i & 1) ? OFF_K1 : OFF_K0);
            const __half* Kn = Kg + (i + 2) * BN * HD;
            #pragma unroll
            for (int l = 0; l < 8; l++) {
                int idx = tid + l * 64;
                int r = idx >> 3, ch = (idx & 7) << 3;
                cp16(kn + r * QPITCH + ch * 2, Kn + r * HD + ch);
            }
            cp_commit();
        }
        if (i + 1 < NKB) {
            const uint32_t vn = sb + (((i + 1) & 1) ? OFF_V1 : OFF_V0);
            const __half* Vn = Vg + (i + 1) * BN * HD;
            #pragma unroll
            for (int l = 0; l < 8; l++) {
                int idx = tid + l * 64;
                int r = idx >> 3, ch = (idx & 7) << 3;
                cp16(vn + r * QPITCH + ch * 2, Vn + r * HD + ch);
            }
            cp_commit();
        }

        // --- softmax(i) per row-tile: e = masked ? 0 : exp2(S) (MUFU pipe) ---
        uint32_t Ap[2][4][4];
        #pragma unroll
        for (int u = 0; u < 2; u++) {
            uint2 m0 = *reinterpret_cast<const uint2*>(g_mb + (rowb + u * 16)     * NW + (i << 1));
            uint2 m1 = *reinterpret_cast<const uint2*>(g_mb + (rowb + u * 16 + 8) * NW + (i << 1));
            #pragma unroll
            for (int j = 0; j < 8; j++) {
                unsigned w0 = (j < 4) ? m0.x : m0.y;
                unsigned w1 = (j < 4) ? m1.x : m1.y;
                int p0 = ((j & 3) << 3) + (qv << 1);
                float e0 = ((w0 >> p0) & 1u)       ? 0.0f : ex2(S[u][j][0]);
                float e1 = ((w0 >> (p0 + 1)) & 1u) ? 0.0f : ex2(S[u][j][1]);
                float e2 = ((w1 >> p0) & 1u)       ? 0.0f : ex2(S[u][j][2]);
                float e3 = ((w1 >> (p0 + 1)) & 1u) ? 0.0f : ex2(S[u][j][3]);
                lsum[u][0] += e0 + e1;
                lsum[u][1] += e2 + e3;
                int t = j >> 1;
                if ((j & 1) == 0) { Ap[u][t][0] = pack_h2(e0, e1); Ap[u][t][1] = pack_h2(e2, e3); }
                else              { Ap[u][t][2] = pack_h2(e0, e1); Ap[u][t][3] = pack_h2(e2, e3); }
            }
        }

        // --- fused MMA issue: QK(i+1) + PV(i), B-frags reused across row-tiles ---
        const uint32_t vcur = sb + ((i & 1) ? OFF_V1 : OFF_V0);
        if (i + 1 < NKB) {
            const uint32_t kcur = sb + (((i + 1) & 1) ? OFF_K1 : OFF_K0);
            #pragma unroll
            for (int u = 0; u < 2; u++)
                #pragma unroll
                for (int j = 0; j < 8; j++)
                    #pragma unroll
                    for (int e = 0; e < 4; e++) S[u][j][e] = 0.0f;
            #pragma unroll
            for (int jp = 0; jp < 4; jp++) {
                #pragma unroll
                for (int t = 0; t < 4; t++) {
                    uint32_t Bk[4];
                    ldsm4(Bk, kcur + jp * (16 * QPITCH) + t * 32 + kbase);
                    uint32_t Bv[4];
                    ldsm4t(Bv, vcur + t * (16 * QPITCH) + jp * 32 + abase);
                    #pragma unroll
                    for (int u = 0; u < 2; u++) {
                        mma16816(S[u][2 * jp],        Aq[u][t], Bk);
                        mma16816(S[u][2 * jp + 1],    Aq[u][t], Bk + 2);
                        mma16816(Oacc[u][2 * jp],     Ap[u][t], Bv);
                        mma16816(Oacc[u][2 * jp + 1], Ap[u][t], Bv + 2);
                    }
                }
            }
        } else {
            #pragma unroll
            for (int jp = 0; jp < 4; jp++) {
                #pragma unroll
                for (int t = 0; t < 4; t++) {
                    uint32_t Bv[4];
                    ldsm4t(Bv, vcur + t * (16 * QPITCH) + jp * 32 + abase);
                    #pragma unroll
                    for (int u = 0; u < 2; u++) {
                        mma16816(Oacc[u][2 * jp],     Ap[u][t], Bv);
                        mma16816(Oacc[u][2 * jp + 1], Ap[u][t], Bv + 2);
                    }
                }
            }
        }

        cp_wait0();
        __syncthreads();
    }

    // ---- epilogue ----
    #pragma unroll
    for (int u = 0; u < 2; u++) {
        float l0 = lsum[u][0], l1 = lsum[u][1];
        l0 += __shfl_xor_sync(0xffffffffu, l0, 1);
        l0 += __shfl_xor_sync(0xffffffffu, l0, 2);
        l1 += __shfl_xor_sync(0xffffffffu, l1, 1);
        l1 += __shfl_xor_sync(0xffffffffu, l1, 2);
        float inv0 = 1.0f / l0;
        float inv1 = 1.0f / l1;

        __half* C0 = g_Ch + h * (SEQ * HD) + (rowb + u * 16) * HD;
        __half* C1 = C0 + 8 * HD;
        #pragma unroll
        for (int j = 0; j < 8; j++) {
            int c = 8 * j + (qv << 1);
            *reinterpret_cast<uint32_t*>(C0 + c) = pack_h2(Oacc[u][j][0] * inv0, Oacc[u][j][1] * inv0);
            *reinterpret_cast<uint32_t*>(C1 + c) = pack_h2(Oacc[u][j][2] * inv1, Oacc[u][j][3] * inv1);
        }
    }
}

// ---------------- launch ----------------
extern "C" void kernel_launch(void* const* d_in, const int* in_sizes, int n_in,
                              void* d_out, int out_size)
{
    (void)in_sizes; (void)n_in; (void)out_size;
    const float* x  = (const float*)d_in[0];
    const int*   mk = (const int*)d_in[1];
    const float* wq = (const float*)d_in[2];
    const float* bq = (const float*)d_in[3];
    const float* wk = (const float*)d_in[4];
    const float* bk = (const float*)d_in[5];
    const float* wv = (const float*)d_in[6];
    const float* bv = (const float*)d_in[7];
    const float* dw = (const float*)d_in[8];
    const float* db = (const float*)d_in[9];
    float* out = (float*)d_out;

    cudaFuncSetAttribute(flash_mma_kernel,
                         cudaFuncAttributeMaxDynamicSharedMemorySize, FL_SMEM);

    convert_kernel<<<3072, 256>>>(x, wq, wk, wv, dw);
    hmma_gemm_kernel<false><<<dim3(DMODEL / 128, SEQ / 128, 3), 256>>>(nullptr, nullptr, bq, bk, bv);
    mask_pack_kernel<<<(SEQ * SEQ) / 256, 256>>>(mk);
    flash_mma_kernel<<<dim3(SEQ / BM, NH), 64, FL_SMEM>>>();
    hmma_gemm_kernel<true><<<dim3(DMODEL / 128, SEQ / 128), 256>>>(out, db, nullptr, nullptr, nullptr);
}